// round 2
// baseline (speedup 1.0000x reference)
#include <cuda_runtime.h>
#include <cstdint>

// CRF NLL:  out[b] = logZ[b] - score_sentence[b]
// B=512, S=1024, T=48. Forward scan in linear domain:
//   p_k = (E @ p_{k-1}) .* exp(emit_k),  E = exp(trans)
// renormalized by p[0] every 4 steps (scale folded into precomputed eE,
// off the critical path); log2 of applied scales accumulated (Kahan, fp32).

static constexpr int T_ = 48;
static constexpr int S_ = 1024;
static constexpr int START_ = 45;
static constexpr int STOP_ = 46;
static constexpr float LOG2E_ = 1.4426950408889634f;
static constexpr float LN2_ = 0.6931471805599453f;

__device__ int g_len[2048];

__device__ __forceinline__ float ex2f_(float x) {
    float y; asm("ex2.approx.ftz.f32 %0, %1;" : "=f"(y) : "f"(x)); return y;
}
__device__ __forceinline__ float lg2f_(float x) {
    float y; asm("lg2.approx.f32 %0, %1;" : "=f"(y) : "f"(x)); return y;
}
__device__ __forceinline__ unsigned long long pack2_(float lo, float hi) {
    unsigned long long r; asm("mov.b64 %0, {%1,%2};" : "=l"(r) : "f"(lo), "f"(hi)); return r;
}
__device__ __forceinline__ void fma2_(unsigned long long& acc, unsigned long long a, unsigned long long b) {
    asm("fma.rn.f32x2 %0, %1, %2, %0;" : "+l"(acc) : "l"(a), "l"(b));
}
__device__ __forceinline__ unsigned long long add2_(unsigned long long a, unsigned long long b) {
    unsigned long long r; asm("add.rn.f32x2 %0, %1, %2;" : "=l"(r) : "l"(a), "l"(b)); return r;
}
__device__ __forceinline__ void unpack2_(unsigned long long v, float& lo, float& hi) {
    asm("mov.b64 {%0,%1}, %2;" : "=f"(lo), "=f"(hi) : "l"(v));
}

// ---------------------------------------------------------------------------
// Kernel 1: score_sentence per batch + sequence length.
// ---------------------------------------------------------------------------
__global__ void score_sent_kernel(const float* __restrict__ feats,
                                  const float* __restrict__ masks,
                                  const int* __restrict__ tags,
                                  const float* __restrict__ trans,
                                  float* __restrict__ out) {
    __shared__ float st[T_ * T_];
    __shared__ float rs[8];
    __shared__ int   rc[8];

    const int b   = blockIdx.x;
    const int tid = threadIdx.x;

    for (int i = tid; i < T_ * T_; i += blockDim.x) st[i] = trans[i];
    __syncthreads();

    const float* mrow = masks + (size_t)b * S_;
    const int*   trow = tags  + (size_t)b * S_;
    const float* frow = feats + (size_t)b * S_ * T_;

    float sum = 0.0f;
    int   cnt = 0;
    for (int s = tid; s < S_; s += blockDim.x) {
        if (mrow[s] != 0.0f) {
            cnt++;
            int tg = trow[s];
            int tp = (s == 0) ? START_ : trow[s - 1];
            sum += frow[s * T_ + tg] + st[tg * T_ + tp];
        }
    }
    #pragma unroll
    for (int o = 16; o > 0; o >>= 1) {
        sum += __shfl_xor_sync(0xffffffffu, sum, o);
        cnt += __shfl_xor_sync(0xffffffffu, cnt, o);
    }
    const int w = tid >> 5;
    if ((tid & 31) == 0) { rs[w] = sum; rc[w] = cnt; }
    __syncthreads();
    if (tid == 0) {
        float tot = 0.0f;
        int   len = 0;
        const int nw = blockDim.x >> 5;
        for (int i = 0; i < nw; i++) { tot += rs[i]; len += rc[i]; }
        int last = trow[len - 1];
        tot += st[STOP_ * T_ + last];
        out[b]   = tot;
        g_len[b] = len;
    }
}

// ---------------------------------------------------------------------------
// Kernel 2: forward scan, one warp per batch.
// ---------------------------------------------------------------------------
__global__ void __launch_bounds__(128, 1)
crf_scan_kernel(const float* __restrict__ feats,
                const float* __restrict__ trans,
                float* __restrict__ out,
                int Btot) {
    __shared__ float4 pbuf[4][2][12];   // [warp][buf][48 floats]

    const int warp = threadIdx.x >> 5;
    const int lane = threadIdx.x & 31;
    const int b = blockIdx.x * 4 + warp;
    if (b >= Btot) return;

    const float* f = feats + (size_t)b * S_ * T_;
    const int len   = g_len[b];
    const int lenm1 = len - 1;

    const int  t0   = lane;
    const int  t1   = lane + 32;
    const bool has1 = (lane < 16);

    // --- Prologue: E rows packed into registers (NEG -> 0) ---
    unsigned long long e0p[24], e1p[24];
    #pragma unroll
    for (int j = 0; j < 24; j++) {
        float a  = expf(trans[t0 * T_ + 2 * j]);
        float bb = expf(trans[t0 * T_ + 2 * j + 1]);
        e0p[j] = pack2_(a, bb);
        float c2 = has1 ? expf(trans[t1 * T_ + 2 * j])     : 0.0f;
        float d2 = has1 ? expf(trans[t1 * T_ + 2 * j + 1]) : 0.0f;
        e1p[j] = pack2_(c2, d2);
    }
    const float es0 = expf(trans[STOP_ * T_ + t0]);
    const float es1 = has1 ? expf(trans[STOP_ * T_ + t1]) : 0.0f;

    // --- init p: delta at START (START=45 lives in t1 range) ---
    {
        float* p0 = reinterpret_cast<float*>(&pbuf[warp][0][0]);
        p0[t0] = 0.0f;
        if (has1) p0[t1] = (t1 == START_) ? 1.0f : 0.0f;
    }
    __syncwarp();

    // --- emission ring: raw*LOG2E for steps 0..7 ---
    float emL[8], emH[8];
    #pragma unroll
    for (int j = 0; j < 8; j++) {
        int kk = (j < len) ? j : lenm1;
        emL[j] = f[kk * T_ + t0] * LOG2E_;
        emH[j] = has1 ? (f[kk * T_ + t1] * LOG2E_) : 0.0f;
    }
    // eE for steps 0 and 1
    float eAc = ex2f_(emL[0]), eBc = ex2f_(emH[0]);
    float eAn = ex2f_(emL[1]), eBn = ex2f_(emH[1]);

    float Asum = 0.0f, Acmp = 0.0f;      // Kahan log2-normalizer accumulator
    float pend = 0.0f, sc = 1.0f;        // pending renorm
    float r0 = 0.0f, r1 = 0.0f;

#define STEPX(J)                                                              \
    {                                                                         \
        if (k0 + (J) >= len) break;                                           \
        const ulonglong2* pv = reinterpret_cast<const ulonglong2*>(           \
            &pbuf[warp][(J) & 1][0]);                                         \
        ulonglong2 v0 = pv[0], v1 = pv[1], v2 = pv[2];                        \
        ulonglong2 v3 = pv[3], v4 = pv[4], v5 = pv[5];                        \
        ulonglong2 v6 = pv[6], v7 = pv[7], v8 = pv[8];                        \
        ulonglong2 v9 = pv[9], v10 = pv[10], v11 = pv[11];                    \
        unsigned long long q0 = 0ull, q1 = 0ull, q2 = 0ull, q3 = 0ull;        \
        unsigned long long q4 = 0ull, q5 = 0ull, q6 = 0ull, q7 = 0ull;        \
        fma2_(q0, e0p[0],  v0.x);  fma2_(q1, e0p[6],  v3.x);                  \
        fma2_(q2, e0p[12], v6.x);  fma2_(q3, e0p[18], v9.x);                  \
        fma2_(q4, e1p[0],  v0.x);  fma2_(q5, e1p[6],  v3.x);                  \
        fma2_(q6, e1p[12], v6.x);  fma2_(q7, e1p[18], v9.x);                  \
        fma2_(q0, e0p[1],  v0.y);  fma2_(q1, e0p[7],  v3.y);                  \
        fma2_(q2, e0p[13], v6.y);  fma2_(q3, e0p[19], v9.y);                  \
        fma2_(q4, e1p[1],  v0.y);  fma2_(q5, e1p[7],  v3.y);                  \
        fma2_(q6, e1p[13], v6.y);  fma2_(q7, e1p[19], v9.y);                  \
        fma2_(q0, e0p[2],  v1.x);  fma2_(q1, e0p[8],  v4.x);                  \
        fma2_(q2, e0p[14], v7.x);  fma2_(q3, e0p[20], v10.x);                 \
        fma2_(q4, e1p[2],  v1.x);  fma2_(q5, e1p[8],  v4.x);                  \
        fma2_(q6, e1p[14], v7.x);  fma2_(q7, e1p[20], v10.x);                 \
        fma2_(q0, e0p[3],  v1.y);  fma2_(q1, e0p[9],  v4.y);                  \
        fma2_(q2, e0p[15], v7.y);  fma2_(q3, e0p[21], v10.y);                 \
        fma2_(q4, e1p[3],  v1.y);  fma2_(q5, e1p[9],  v4.y);                  \
        fma2_(q6, e1p[15], v7.y);  fma2_(q7, e1p[21], v10.y);                 \
        fma2_(q0, e0p[4],  v2.x);  fma2_(q1, e0p[10], v5.x);                  \
        fma2_(q2, e0p[16], v8.x);  fma2_(q3, e0p[22], v11.x);                 \
        fma2_(q4, e1p[4],  v2.x);  fma2_(q5, e1p[10], v5.x);                  \
        fma2_(q6, e1p[16], v8.x);  fma2_(q7, e1p[22], v11.x);                 \
        fma2_(q0, e0p[5],  v2.y);  fma2_(q1, e0p[11], v5.y);                  \
        fma2_(q2, e0p[17], v8.y);  fma2_(q3, e0p[23], v11.y);                 \
        fma2_(q4, e1p[5],  v2.y);  fma2_(q5, e1p[11], v5.y);                  \
        fma2_(q6, e1p[17], v8.y);  fma2_(q7, e1p[23], v11.y);                 \
        unsigned long long s0 = add2_(add2_(q0, q1), add2_(q2, q3));          \
        unsigned long long s1 = add2_(add2_(q4, q5), add2_(q6, q7));          \
        float d0l, d0h, d1l, d1h;                                             \
        unpack2_(s0, d0l, d0h);                                               \
        unpack2_(s1, d1l, d1h);                                               \
        r0 = (d0l + d0h) * eAc;                                               \
        r1 = (d1l + d1h) * eBc;                                               \
        float* pn = reinterpret_cast<float*>(&pbuf[warp][((J) & 1) ^ 1][0]);  \
        pn[t0] = r0;                                                          \
        if (has1) pn[t1] = r1;                                                \
        if ((J) == 1 || (J) == 5) {                                           \
            float cc = __shfl_sync(0xffffffffu, r0, 0);                       \
            pend = lg2f_(cc);                                                 \
            sc   = ex2f_(-pend);                                              \
        }                                                                     \
        if ((J) == 3 || (J) == 7) {                                           \
            float y = pend - Acmp;                                            \
            float t = Asum + y;                                               \
            Acmp = (t - Asum) - y;                                            \
            Asum = t;                                                         \
        }                                                                     \
        float nA = ex2f_(emL[((J) + 2) & 7]);                                 \
        float nB = ex2f_(emH[((J) + 2) & 7]);                                 \
        if ((J) == 1 || (J) == 5) { nA *= sc; nB *= sc; }                     \
        eAc = eAn; eBc = eBn; eAn = nA; eBn = nB;                             \
        int kk = k0 + 8 + (J);                                                \
        if (kk > lenm1) kk = lenm1;                                           \
        emL[(J)] = f[kk * T_ + t0] * LOG2E_;                                  \
        emH[(J)] = has1 ? (f[kk * T_ + t1] * LOG2E_) : 0.0f;                  \
        __syncwarp();                                                         \
    }

    int k0 = 0;
    while (k0 < len) {
        STEPX(0) STEPX(1) STEPX(2) STEPX(3)
        STEPX(4) STEPX(5) STEPX(6) STEPX(7)
        k0 += 8;
    }
#undef STEPX

    // --- final: logZ = ln2 * (Asum + log2( sum_t p_L[t] * E_stop[t] )) ---
    float part = r0 * es0 + (has1 ? r1 * es1 : 0.0f);
    #pragma unroll
    for (int o = 16; o > 0; o >>= 1) part += __shfl_xor_sync(0xffffffffu, part, o);

    if (lane == 0) {
        float logZ = (Asum + lg2f_(part)) * LN2_;
        out[b] = logZ - out[b];
    }
}

// ---------------------------------------------------------------------------
extern "C" void kernel_launch(void* const* d_in, const int* in_sizes, int n_in,
                              void* d_out, int out_size) {
    const float* feats = (const float*)d_in[0];
    const float* masks = (const float*)d_in[1];
    const int*   tags  = (const int*)d_in[2];
    const float* trans = (const float*)d_in[3];
    float* out = (float*)d_out;
    const int B = out_size;                 // 512

    score_sent_kernel<<<B, 256>>>(feats, masks, tags, trans, out);
    crf_scan_kernel<<<(B + 3) / 4, 128>>>(feats, trans, out, B);
}

// round 3
// speedup vs baseline: 1.7485x; 1.7485x over previous
#include <cuda_runtime.h>
#include <cstdint>

// CRF NLL:  out[b] = logZ[b] - score_sentence[b]
// B=512, S=1024, T=48. Forward scan in linear domain:
//   p_k = (E @ p_{k-1}) .* exp(emit_k),  E = exp(trans)
// Two warps cooperate per batch: warp w owns rows [24w, 24w+24), lane<24 owns
// one row (E row in 24 packed f32x2 regs). p handed off via smem double
// buffer + one __syncthreads per step. Renormalized every 4 steps by p[0]
// (read from the broadcast LDS, no shuffle); log2 scales Kahan-accumulated.

static constexpr int T_ = 48;
static constexpr int S_ = 1024;
static constexpr int START_ = 45;
static constexpr int STOP_ = 46;
static constexpr float LOG2E_ = 1.4426950408889634f;
static constexpr float LN2_ = 0.6931471805599453f;

__device__ int g_len[2048];

__device__ __forceinline__ float ex2f_(float x) {
    float y; asm("ex2.approx.ftz.f32 %0, %1;" : "=f"(y) : "f"(x)); return y;
}
__device__ __forceinline__ float lg2f_(float x) {
    float y; asm("lg2.approx.f32 %0, %1;" : "=f"(y) : "f"(x)); return y;
}
__device__ __forceinline__ unsigned long long pack2_(float lo, float hi) {
    unsigned long long r; asm("mov.b64 %0, {%1,%2};" : "=l"(r) : "f"(lo), "f"(hi)); return r;
}
__device__ __forceinline__ void fma2_(unsigned long long& acc, unsigned long long a, unsigned long long b) {
    asm("fma.rn.f32x2 %0, %1, %2, %0;" : "+l"(acc) : "l"(a), "l"(b));
}
__device__ __forceinline__ unsigned long long add2_(unsigned long long a, unsigned long long b) {
    unsigned long long r; asm("add.rn.f32x2 %0, %1, %2;" : "=l"(r) : "l"(a), "l"(b)); return r;
}
__device__ __forceinline__ void unpack2_(unsigned long long v, float& lo, float& hi) {
    asm("mov.b64 {%0,%1}, %2;" : "=f"(lo), "=f"(hi) : "l"(v));
}

// ---------------------------------------------------------------------------
// Kernel 1: score_sentence per batch + sequence length.
// ---------------------------------------------------------------------------
__global__ void score_sent_kernel(const float* __restrict__ feats,
                                  const float* __restrict__ masks,
                                  const int* __restrict__ tags,
                                  const float* __restrict__ trans,
                                  float* __restrict__ out) {
    __shared__ float st[T_ * T_];
    __shared__ float rs[8];
    __shared__ int   rc[8];

    const int b   = blockIdx.x;
    const int tid = threadIdx.x;

    for (int i = tid; i < T_ * T_; i += blockDim.x) st[i] = trans[i];
    __syncthreads();

    const float* mrow = masks + (size_t)b * S_;
    const int*   trow = tags  + (size_t)b * S_;
    const float* frow = feats + (size_t)b * S_ * T_;

    float sum = 0.0f;
    int   cnt = 0;
    for (int s = tid; s < S_; s += blockDim.x) {
        if (mrow[s] != 0.0f) {
            cnt++;
            int tg = trow[s];
            int tp = (s == 0) ? START_ : trow[s - 1];
            sum += frow[s * T_ + tg] + st[tg * T_ + tp];
        }
    }
    #pragma unroll
    for (int o = 16; o > 0; o >>= 1) {
        sum += __shfl_xor_sync(0xffffffffu, sum, o);
        cnt += __shfl_xor_sync(0xffffffffu, cnt, o);
    }
    const int w = tid >> 5;
    if ((tid & 31) == 0) { rs[w] = sum; rc[w] = cnt; }
    __syncthreads();
    if (tid == 0) {
        float tot = 0.0f;
        int   len = 0;
        const int nw = blockDim.x >> 5;
        for (int i = 0; i < nw; i++) { tot += rs[i]; len += rc[i]; }
        int last = trow[len - 1];
        tot += st[STOP_ * T_ + last];
        out[b]   = tot;
        g_len[b] = len;
    }
}

// ---------------------------------------------------------------------------
// Kernel 2: forward scan, 2 warps per batch (64-thread blocks).
// ---------------------------------------------------------------------------
__global__ void __launch_bounds__(64, 8)
crf_scan_kernel(const float* __restrict__ feats,
                const float* __restrict__ trans,
                float* __restrict__ out) {
    __shared__ float4 pbuf4[2][12];              // double-buffered p (48 floats)
    __shared__ float  wpart[2];

    const int b    = blockIdx.x;
    const int tid  = threadIdx.x;
    const int warp = tid >> 5;
    const int lane = tid & 31;

    const int  t      = warp * 24 + lane;        // owned row
    const bool active = (lane < 24);

    const float* f = feats + (size_t)b * S_ * T_;
    const int len  = g_len[b];

    // --- Prologue: my E row (24 packed f32x2); NEG -> exact 0 ---
    unsigned long long er[24];
    #pragma unroll
    for (int j = 0; j < 24; j++) {
        float a = 0.0f, c = 0.0f;
        if (active) {
            a = expf(trans[t * T_ + 2 * j]);
            c = expf(trans[t * T_ + 2 * j + 1]);
        }
        er[j] = pack2_(a, c);
    }
    const float esr = active ? expf(trans[STOP_ * T_ + t]) : 0.0f;

    // --- init p0 = delta(START) ---
    {
        float* p0 = reinterpret_cast<float*>(&pbuf4[0][0]);
        if (tid < T_) p0[tid] = (tid == START_) ? 1.0f : 0.0f;
    }

    // --- emission ring (raw * LOG2E) for steps 0..3 ---
    float em[4];
    #pragma unroll
    for (int j = 0; j < 4; j++) {
        float ev = 0.0f;
        if (active && j < len) ev = f[j * T_ + t];
        em[j] = ev * LOG2E_;
    }
    float eEc = ex2f_(em[0]);                    // eE for current step

    float Asum = 0.0f, Acmp = 0.0f;              // Kahan log2-normalizer
    float pend = 0.0f;                           // measured, to fold on use
    float r = 0.0f;

    __syncthreads();

    const int nfull = len >> 2;
    const int rem   = len & 3;
    int kbase = 0;

#define STEPG(J)                                                              \
    {                                                                         \
        const ulonglong2* pv =                                                \
            reinterpret_cast<const ulonglong2*>(&pbuf4[(J) & 1][0]);          \
        ulonglong2 v0 = pv[0], v1 = pv[1], v2 = pv[2];                        \
        ulonglong2 v3 = pv[3], v4 = pv[4], v5 = pv[5];                        \
        ulonglong2 v6 = pv[6], v7 = pv[7], v8 = pv[8];                        \
        ulonglong2 v9 = pv[9], v10 = pv[10], v11 = pv[11];                    \
        unsigned long long q0 = 0ull, q1 = 0ull, q2 = 0ull, q3 = 0ull;        \
        fma2_(q0, er[0],  v0.x);  fma2_(q1, er[6],  v3.x);                    \
        fma2_(q2, er[12], v6.x);  fma2_(q3, er[18], v9.x);                    \
        fma2_(q0, er[1],  v0.y);  fma2_(q1, er[7],  v3.y);                    \
        fma2_(q2, er[13], v6.y);  fma2_(q3, er[19], v9.y);                    \
        fma2_(q0, er[2],  v1.x);  fma2_(q1, er[8],  v4.x);                    \
        fma2_(q2, er[14], v7.x);  fma2_(q3, er[20], v10.x);                   \
        fma2_(q0, er[3],  v1.y);  fma2_(q1, er[9],  v4.y);                    \
        fma2_(q2, er[15], v7.y);  fma2_(q3, er[21], v10.y);                   \
        fma2_(q0, er[4],  v2.x);  fma2_(q1, er[10], v5.x);                    \
        fma2_(q2, er[16], v8.x);  fma2_(q3, er[22], v11.x);                   \
        fma2_(q0, er[5],  v2.y);  fma2_(q1, er[11], v5.y);                    \
        fma2_(q2, er[17], v8.y);  fma2_(q3, er[23], v11.y);                   \
        unsigned long long s = add2_(add2_(q0, q1), add2_(q2, q3));           \
        float dl, dh;                                                         \
        unpack2_(s, dl, dh);                                                  \
        r = (dl + dh) * eEc;                                                  \
        if ((J) == 0) {   /* fold scale applied in this step's eEc */         \
            float y = pend - Acmp;                                            \
            float tt = Asum + y;                                              \
            Acmp = (tt - Asum) - y;                                           \
            Asum = tt;                                                        \
        }                                                                     \
        float* pn = reinterpret_cast<float*>(&pbuf4[((J) & 1) ^ 1][0]);       \
        if (active) pn[t] = r;                                                \
        float nE = ex2f_(em[((J) + 1) & 3]);                                  \
        if ((J) == 3) {  /* measure p[k-1][0] from this step's LDS */         \
            float p0l, p0h;                                                   \
            unpack2_(v0.x, p0l, p0h);                                         \
            float m  = lg2f_(p0l);                                            \
            nE *= ex2f_(-m);                                                  \
            pend = m;                                                         \
        }                                                                     \
        eEc = nE;                                                             \
        {                                                                     \
            int kpre = kbase + (J) + 4;                                       \
            float ev = 0.0f;                                                  \
            if (active && kpre < len) ev = f[(size_t)kpre * T_ + t];          \
            em[(J)] = ev * LOG2E_;                                            \
        }                                                                     \
        __syncthreads();                                                      \
    }

    for (int g = 0; g < nfull; g++) {
        STEPG(0) STEPG(1) STEPG(2) STEPG(3)
        kbase += 4;
    }
#undef STEPG

    // --- remainder (0..3 steps, dynamic parity) ---
    for (int j = 0; j < rem; j++) {
        const ulonglong2* pv =
            reinterpret_cast<const ulonglong2*>(&pbuf4[j & 1][0]);
        unsigned long long q0 = 0ull, q1 = 0ull, q2 = 0ull, q3 = 0ull;
        #pragma unroll
        for (int i = 0; i < 6; i++) {
            ulonglong2 a = pv[i], c = pv[i + 6];
            fma2_(q0, er[2 * i],      a.x);
            fma2_(q0, er[2 * i + 1],  a.y);
            fma2_(q1, er[12 + 2 * i], c.x);
            fma2_(q1, er[13 + 2 * i], c.y);
        }
        unsigned long long s = add2_(add2_(q0, q1), add2_(q2, q3));
        float dl, dh;
        unpack2_(s, dl, dh);
        r = (dl + dh) * eEc;
        if (j == 0) {                 // scale from last group folded here
            float y = pend - Acmp;
            float tt = Asum + y;
            Acmp = (tt - Asum) - y;
            Asum = tt;
        }
        float* pn = reinterpret_cast<float*>(&pbuf4[(j & 1) ^ 1][0]);
        if (active) pn[t] = r;
        eEc = ex2f_(em[(j + 1) & 3]);
        __syncthreads();
    }

    // --- final: logZ = ln2 * (Asum + log2( sum_t p_L[t] * E_stop[t] )) ---
    float part = active ? r * esr : 0.0f;
    #pragma unroll
    for (int o = 16; o > 0; o >>= 1) part += __shfl_xor_sync(0xffffffffu, part, o);
    if (lane == 0) wpart[warp] = part;
    __syncthreads();
    if (tid == 0) {
        float tot  = wpart[0] + wpart[1];
        float logZ = (Asum + lg2f_(tot)) * LN2_;
        out[b] = logZ - out[b];
    }
}

// ---------------------------------------------------------------------------
extern "C" void kernel_launch(void* const* d_in, const int* in_sizes, int n_in,
                              void* d_out, int out_size) {
    const float* feats = (const float*)d_in[0];
    const float* masks = (const float*)d_in[1];
    const int*   tags  = (const int*)d_in[2];
    const float* trans = (const float*)d_in[3];
    float* out = (float*)d_out;
    const int B = out_size;                 // 512

    score_sent_kernel<<<B, 256>>>(feats, masks, tags, trans, out);
    crf_scan_kernel<<<B, 64>>>(feats, trans, out);
}